// round 4
// baseline (speedup 1.0000x reference)
#include <cuda_runtime.h>
#include <cuda_bf16.h>
#include <math.h>

// Shapes (fixed by the problem)
// B=4, N=256, D=768, H=12, DD=64, HD=64, M = B*N = 1024
#define MROWS 1024
#define DMODEL 768
#define NSEQ 256
#define NHEAD 12
#define HDIM 64
#define DDIM 64

// ---------------- scratch (no allocations allowed) ----------------
__device__ float g_xn   [MROWS * DMODEL];
__device__ float g_qkv  [MROWS * 3 * DMODEL];
__device__ float g_s1   [MROWS * DMODEL];     // silu(xn@gate_w1+b1)
__device__ float g_gated[MROWS * DMODEL];
__device__ float g_biasT[4 * NHEAD * NSEQ * NSEQ];  // [b][h][i][j]
__device__ float g_ctx  [MROWS * DMODEL];
__device__ float g_a    [MROWS * DMODEL];     // ctx * sigmoid(gated)
__device__ float g_x2   [MROWS * DMODEL];
__device__ float g_y    [MROWS * DMODEL];
__device__ float g_ffh  [MROWS * 2 * DMODEL];

// ---------------- helpers ----------------
__device__ __forceinline__ float warp_sum(float v) {
    #pragma unroll
    for (int o = 16; o > 0; o >>= 1) v += __shfl_xor_sync(0xffffffffu, v, o);
    return v;
}
__device__ __forceinline__ float warp_max(float v) {
    #pragma unroll
    for (int o = 16; o > 0; o >>= 1) v = fmaxf(v, __shfl_xor_sync(0xffffffffu, v, o));
    return v;
}

// ---------------- LayerNorm: one block per row of 768 ----------------
__global__ __launch_bounds__(256) void ln_kernel(
    const float* __restrict__ x, const float* __restrict__ gw,
    const float* __restrict__ bw, float* __restrict__ out)
{
    int row = blockIdx.x;
    int tid = threadIdx.x;
    const float* xr = x + (size_t)row * DMODEL;
    float v0 = xr[tid], v1 = xr[tid + 256], v2 = xr[tid + 512];
    float s  = v0 + v1 + v2;
    float s2 = v0 * v0 + v1 * v1 + v2 * v2;
    __shared__ float sm[8], sm2[8], stat[2];
    float ws = warp_sum(s), ws2 = warp_sum(s2);
    int wid = tid >> 5, lane = tid & 31;
    if (!lane) { sm[wid] = ws; sm2[wid] = ws2; }
    __syncthreads();
    if (tid == 0) {
        float S = 0.f, S2 = 0.f;
        #pragma unroll
        for (int i = 0; i < 8; ++i) { S += sm[i]; S2 += sm2[i]; }
        float mu  = S * (1.f / DMODEL);
        float var = S2 * (1.f / DMODEL) - mu * mu;
        stat[0] = mu;
        stat[1] = rsqrtf(var + 1e-5f);
    }
    __syncthreads();
    float mu = stat[0], rstd = stat[1];
    float* orow = out + (size_t)row * DMODEL;
    orow[tid]       = (v0 - mu) * rstd * gw[tid]       + bw[tid];
    orow[tid + 256] = (v1 - mu) * rstd * gw[tid + 256] + bw[tid + 256];
    orow[tid + 512] = (v2 - mu) * rstd * gw[tid + 512] + bw[tid + 512];
}

// ---------------- generic SGEMM: C = act(A[M,K]@W[K,N] + bias) (+ res) ----
// 64x64 tile, BK=16, 256 threads, 4x4 per-thread micro-tile.
template<int ACT, bool RES>
__global__ __launch_bounds__(256) void gemm_kernel(
    const float* __restrict__ A, const float* __restrict__ W,
    const float* __restrict__ bias, const float* __restrict__ res,
    float* __restrict__ C, int M, int N, int K)
{
    __shared__ float As[16][64];
    __shared__ float Bs[16][64];
    int t  = threadIdx.x;
    int bm = blockIdx.y << 6;
    int bn = blockIdx.x << 6;
    int ty = t >> 4, tx = t & 15;
    int arow = t >> 2,  acol = (t & 3) << 2;
    int brow = t >> 4,  bcol = (t & 15) << 2;
    const float* Ap = A + (size_t)(bm + arow) * K + acol;
    const float* Wp = W + (size_t)brow * N + bn + bcol;
    float acc[4][4] = {};
    for (int k0 = 0; k0 < K; k0 += 16) {
        float4 av = *reinterpret_cast<const float4*>(Ap + k0);
        As[acol + 0][arow] = av.x;
        As[acol + 1][arow] = av.y;
        As[acol + 2][arow] = av.z;
        As[acol + 3][arow] = av.w;
        *reinterpret_cast<float4*>(&Bs[brow][bcol]) =
            *reinterpret_cast<const float4*>(Wp + (size_t)k0 * N);
        __syncthreads();
        #pragma unroll
        for (int kk = 0; kk < 16; ++kk) {
            float4 a = *reinterpret_cast<const float4*>(&As[kk][ty << 2]);
            float4 b = *reinterpret_cast<const float4*>(&Bs[kk][tx << 2]);
            acc[0][0] = fmaf(a.x, b.x, acc[0][0]);
            acc[0][1] = fmaf(a.x, b.y, acc[0][1]);
            acc[0][2] = fmaf(a.x, b.z, acc[0][2]);
            acc[0][3] = fmaf(a.x, b.w, acc[0][3]);
            acc[1][0] = fmaf(a.y, b.x, acc[1][0]);
            acc[1][1] = fmaf(a.y, b.y, acc[1][1]);
            acc[1][2] = fmaf(a.y, b.z, acc[1][2]);
            acc[1][3] = fmaf(a.y, b.w, acc[1][3]);
            acc[2][0] = fmaf(a.z, b.x, acc[2][0]);
            acc[2][1] = fmaf(a.z, b.y, acc[2][1]);
            acc[2][2] = fmaf(a.z, b.z, acc[2][2]);
            acc[2][3] = fmaf(a.z, b.w, acc[2][3]);
            acc[3][0] = fmaf(a.w, b.x, acc[3][0]);
            acc[3][1] = fmaf(a.w, b.y, acc[3][1]);
            acc[3][2] = fmaf(a.w, b.z, acc[3][2]);
            acc[3][3] = fmaf(a.w, b.w, acc[3][3]);
        }
        __syncthreads();
    }
    #pragma unroll
    for (int i = 0; i < 4; ++i) {
        int row = bm + (ty << 2) + i;
        #pragma unroll
        for (int j = 0; j < 4; ++j) {
            int col = bn + (tx << 2) + j;
            float v = acc[i][j] + bias[col];
            if (ACT == 1) v = v / (1.f + __expf(-v));                      // silu
            if (ACT == 2) v = 0.5f * v * (1.f + erff(v * 0.70710678118654752f)); // gelu exact
            if (RES) v += res[(size_t)row * N + col];
            C[(size_t)row * N + col] = v;
        }
    }
}

// ---------------- fused distance-bias MLP (the 30-GFLOP monster) ---------
// bias[b,i,j,h] = silu(dist[b,i,j,:] @ W1 + b1) @ W2 + b2, stored [b][h][i][j]
// One block per (b,i) pair (256 j-rows). 128 threads x 2 rows each; dist rows
// live in registers. W1 chunk is stored TRANSPOSED in smem ([c][d], stride 68)
// so each hidden unit's 64 weights are 16 contiguous LDS.128 broadcasts
// instead of 64 strided scalar LDS.
#define W1STRIDE 68
__global__ __launch_bounds__(128, 2) void rbias_kernel(
    const float* __restrict__ dist, const float* __restrict__ W1,
    const float* __restrict__ b1,   const float* __restrict__ W2,
    const float* __restrict__ b2,   float* __restrict__ biasT)
{
    int bi  = blockIdx.x;            // b*256 + i
    int bb  = bi >> 8, ii = bi & 255;
    int tid = threadIdx.x;

    __shared__ float sW1[64 * W1STRIDE]; // [c][d] transposed, padded stride
    __shared__ float sW2[64 * 12];       // [c][o]
    __shared__ float sb1[64];

    float d0[64], d1[64];
    const float* dp = dist + (((size_t)bi << 8) + (tid << 1)) * DDIM;
    #pragma unroll
    for (int q = 0; q < 16; ++q) {
        float4 t0 = *reinterpret_cast<const float4*>(dp + q * 4);
        d0[q * 4 + 0] = t0.x; d0[q * 4 + 1] = t0.y;
        d0[q * 4 + 2] = t0.z; d0[q * 4 + 3] = t0.w;
        float4 t1 = *reinterpret_cast<const float4*>(dp + DDIM + q * 4);
        d1[q * 4 + 0] = t1.x; d1[q * 4 + 1] = t1.y;
        d1[q * 4 + 2] = t1.z; d1[q * 4 + 3] = t1.w;
    }

    float acc0[12] = {}, acc1[12] = {};

    #pragma unroll 1
    for (int cc = 0; cc < 12; ++cc) {
        // W1 chunk: global [d][hidden] read coalesced, smem write transposed
        for (int idx = tid; idx < 4096; idx += 128) {
            int d = idx >> 6, c = idx & 63;
            sW1[c * W1STRIDE + d] = W1[(size_t)d * DMODEL + (cc << 6) + c];
        }
        for (int idx = tid; idx < 768; idx += 128)
            sW2[idx] = W2[(size_t)cc * 768 + idx];   // W2[(cc*64+c)*12+o]
        if (tid < 64) sb1[tid] = b1[(cc << 6) + tid];
        __syncthreads();

        #pragma unroll 2
        for (int c = 0; c < 64; ++c) {
            float h0a = sb1[c], h0b = 0.f, h1a = sb1[c], h1b = 0.f;
            const float4* w1c = reinterpret_cast<const float4*>(sW1 + c * W1STRIDE);
            #pragma unroll
            for (int q = 0; q < 16; ++q) {
                float4 w = w1c[q];
                int d = q << 2;
                h0a = fmaf(d0[d + 0], w.x, h0a);
                h1a = fmaf(d1[d + 0], w.x, h1a);
                h0b = fmaf(d0[d + 1], w.y, h0b);
                h1b = fmaf(d1[d + 1], w.y, h1b);
                h0a = fmaf(d0[d + 2], w.z, h0a);
                h1a = fmaf(d1[d + 2], w.z, h1a);
                h0b = fmaf(d0[d + 3], w.w, h0b);
                h1b = fmaf(d1[d + 3], w.w, h1b);
            }
            float h0 = h0a + h0b, h1 = h1a + h1b;
            float s0 = h0 / (1.f + __expf(-h0));
            float s1 = h1 / (1.f + __expf(-h1));
            const float4* w2c = reinterpret_cast<const float4*>(sW2 + c * 12);
            #pragma unroll
            for (int qq = 0; qq < 3; ++qq) {
                float4 w = w2c[qq];
                int o = qq << 2;
                acc0[o + 0] = fmaf(s0, w.x, acc0[o + 0]);
                acc1[o + 0] = fmaf(s1, w.x, acc1[o + 0]);
                acc0[o + 1] = fmaf(s0, w.y, acc0[o + 1]);
                acc1[o + 1] = fmaf(s1, w.y, acc1[o + 1]);
                acc0[o + 2] = fmaf(s0, w.z, acc0[o + 2]);
                acc1[o + 2] = fmaf(s1, w.z, acc1[o + 2]);
                acc0[o + 3] = fmaf(s0, w.w, acc0[o + 3]);
                acc1[o + 3] = fmaf(s1, w.w, acc1[o + 3]);
            }
        }
        __syncthreads();
    }

    int j0 = tid << 1;
    #pragma unroll
    for (int o = 0; o < 12; ++o) {
        float bo = b2[o];
        size_t base = (((size_t)bb * NHEAD + o) * NSEQ + ii) * NSEQ;
        biasT[base + j0]     = acc0[o] + bo;
        biasT[base + j0 + 1] = acc1[o] + bo;
    }
}

// ---------------- attention: one block per (b,h,i) query row -------------
__global__ __launch_bounds__(128) void attn_kernel(
    const float* __restrict__ qkv, const float* __restrict__ biasT,
    const int* __restrict__ mask, float* __restrict__ ctx)
{
    int i = blockIdx.x, h = blockIdx.y, b = blockIdx.z;
    int tid = threadIdx.x;
    __shared__ float qs[64];
    __shared__ float ps[256];
    __shared__ float red[4];
    __shared__ float part[2][64];

    size_t qoff = ((size_t)(b * NSEQ + i)) * 2304 + (size_t)h * HDIM;
    if (tid < 64) qs[tid] = qkv[qoff + tid];
    __syncthreads();

    float lv[2];
    #pragma unroll
    for (int u = 0; u < 2; ++u) {
        int j = tid + (u << 7);
        const float* kp = qkv + ((size_t)(b * NSEQ + j)) * 2304 + DMODEL + h * HDIM;
        float a0 = 0.f, a1 = 0.f;
        #pragma unroll
        for (int d = 0; d < 64; d += 4) {
            float4 kv4 = *reinterpret_cast<const float4*>(kp + d);
            a0 = fmaf(qs[d],     kv4.x, a0);
            a1 = fmaf(qs[d + 1], kv4.y, a1);
            a0 = fmaf(qs[d + 2], kv4.z, a0);
            a1 = fmaf(qs[d + 3], kv4.w, a1);
        }
        float lg = (a0 + a1) * 0.125f
                 + biasT[(((size_t)b * NHEAD + h) * NSEQ + i) * NSEQ + j];
        if (mask[((size_t)(b * NSEQ + i)) * NSEQ + j] == 0) lg = -1e30f;
        lv[u] = lg;
    }

    int wid = tid >> 5, lane = tid & 31;
    float m = warp_max(fmaxf(lv[0], lv[1]));
    if (!lane) red[wid] = m;
    __syncthreads();
    m = fmaxf(fmaxf(red[0], red[1]), fmaxf(red[2], red[3]));
    __syncthreads();                     // red reuse below

    float e0 = __expf(lv[0] - m), e1 = __expf(lv[1] - m);
    ps[tid] = e0; ps[tid + 128] = e1;
    float s = warp_sum(e0 + e1);
    if (!lane) red[wid] = s;
    __syncthreads();
    float inv = 1.f / (red[0] + red[1] + red[2] + red[3]);

    int d = tid & 63, pr = tid >> 6;
    const float* vp = qkv + 2 * DMODEL + (size_t)h * HDIM + d;
    float a0 = 0.f, a1 = 0.f;
    int j0 = pr << 7;
    #pragma unroll 4
    for (int j = j0; j < j0 + 128; j += 2) {
        a0 = fmaf(ps[j],     vp[((size_t)(b * NSEQ + j)) * 2304],     a0);
        a1 = fmaf(ps[j + 1], vp[((size_t)(b * NSEQ + j + 1)) * 2304], a1);
    }
    part[pr][d] = a0 + a1;
    __syncthreads();
    if (tid < 64)
        ctx[((size_t)(b * NSEQ + i)) * DMODEL + h * HDIM + tid] =
            (part[0][tid] + part[1][tid]) * inv;
}

// ---------------- a = ctx * sigmoid(gated) ----------------
__global__ __launch_bounds__(256) void gate_mul_kernel(
    const float* __restrict__ ctx, const float* __restrict__ gated,
    float* __restrict__ a, int n)
{
    int idx = blockIdx.x * 256 + threadIdx.x;
    if (idx < n) {
        float g = gated[idx];
        a[idx] = ctx[idx] * (1.f / (1.f + __expf(-g)));
    }
}

// ---------------- launch ----------------
extern "C" void kernel_launch(void* const* d_in, const int* in_sizes, int n_in,
                              void* d_out, int out_size)
{
    const float* x       = (const float*)d_in[0];
    const float* dist    = (const float*)d_in[1];
    const int*   mask    = (const int*)  d_in[2];
    const float* qkv_w   = (const float*)d_in[3];
    const float* qkv_b   = (const float*)d_in[4];
    const float* out_w   = (const float*)d_in[5];
    const float* out_b   = (const float*)d_in[6];
    const float* rb_w1   = (const float*)d_in[7];
    const float* rb_b1   = (const float*)d_in[8];
    const float* rb_w2   = (const float*)d_in[9];
    const float* rb_b2   = (const float*)d_in[10];
    const float* gate_w1 = (const float*)d_in[11];
    const float* gate_b1 = (const float*)d_in[12];
    const float* gate_w2 = (const float*)d_in[13];
    const float* gate_b2 = (const float*)d_in[14];
    const float* ff_w1   = (const float*)d_in[15];
    const float* ff_b1   = (const float*)d_in[16];
    const float* ff_w2   = (const float*)d_in[17];
    const float* ff_b2   = (const float*)d_in[18];
    const float* ln1_g   = (const float*)d_in[19];
    const float* ln1_b   = (const float*)d_in[20];
    const float* ln2_g   = (const float*)d_in[21];
    const float* ln2_b   = (const float*)d_in[22];
    float* out = (float*)d_out;

    float *xn, *qkv, *s1, *gated, *biasT, *ctx, *a, *x2, *y, *ffh;
    cudaGetSymbolAddress((void**)&xn,    g_xn);
    cudaGetSymbolAddress((void**)&qkv,   g_qkv);
    cudaGetSymbolAddress((void**)&s1,    g_s1);
    cudaGetSymbolAddress((void**)&gated, g_gated);
    cudaGetSymbolAddress((void**)&biasT, g_biasT);
    cudaGetSymbolAddress((void**)&ctx,   g_ctx);
    cudaGetSymbolAddress((void**)&a,     g_a);
    cudaGetSymbolAddress((void**)&x2,    g_x2);
    cudaGetSymbolAddress((void**)&y,     g_y);
    cudaGetSymbolAddress((void**)&ffh,   g_ffh);

    // LN1
    ln_kernel<<<MROWS, 256>>>(x, ln1_g, ln1_b, xn);
    // qkv = xn @ qkv_w + b
    gemm_kernel<0, false><<<dim3(36, 16), 256>>>(xn, qkv_w, qkv_b, nullptr, qkv,
                                                 MROWS, 3 * DMODEL, DMODEL);
    // s1 = silu(xn @ gate_w1 + b)
    gemm_kernel<1, false><<<dim3(12, 16), 256>>>(xn, gate_w1, gate_b1, nullptr, s1,
                                                 MROWS, DMODEL, DMODEL);
    // fused distance-bias MLP
    rbias_kernel<<<MROWS, 128>>>(dist, rb_w1, rb_b1, rb_w2, rb_b2, biasT);
    // attention
    attn_kernel<<<dim3(NSEQ, NHEAD, 4), 128>>>(qkv, biasT, mask, ctx);
    // gated = s1 @ gate_w2 + b
    gemm_kernel<0, false><<<dim3(12, 16), 256>>>(s1, gate_w2, gate_b2, nullptr, gated,
                                                 MROWS, DMODEL, DMODEL);
    // a = ctx * sigmoid(gated)
    gate_mul_kernel<<<(MROWS * DMODEL + 255) / 256, 256>>>(ctx, gated, a, MROWS * DMODEL);
    // x2 = x + a @ out_w + out_b
    gemm_kernel<0, true><<<dim3(12, 16), 256>>>(a, out_w, out_b, x, x2,
                                                MROWS, DMODEL, DMODEL);
    // LN2
    ln_kernel<<<MROWS, 256>>>(x2, ln2_g, ln2_b, y);
    // ffh = gelu(y @ ff_w1 + b)
    gemm_kernel<2, false><<<dim3(24, 16), 256>>>(y, ff_w1, ff_b1, nullptr, ffh,
                                                 MROWS, 2 * DMODEL, DMODEL);
    // out = x2 + ffh @ ff_w2 + b
    gemm_kernel<0, true><<<dim3(12, 16), 256>>>(ffh, ff_w2, ff_b2, x2, out,
                                                MROWS, DMODEL, 2 * DMODEL);
}

// round 9
// speedup vs baseline: 1.6433x; 1.6433x over previous
#include <cuda_runtime.h>
#include <cuda_bf16.h>
#include <math.h>

// Shapes (fixed by the problem)
// B=4, N=256, D=768, H=12, DD=64, HD=64, M = B*N = 1024
#define MROWS 1024
#define DMODEL 768
#define NSEQ 256
#define NHEAD 12
#define HDIM 64
#define DDIM 64

// ---------------- scratch (no allocations allowed) ----------------
__device__ float g_xn   [MROWS * DMODEL];
__device__ float g_qkv  [MROWS * 3 * DMODEL];
__device__ float g_s1   [MROWS * DMODEL];     // silu(xn@gate_w1+b1)
__device__ float g_gated[MROWS * DMODEL];
__device__ float g_biasT[4 * NHEAD * NSEQ * NSEQ];  // [b][h][i][j]
__device__ float g_ctx  [MROWS * DMODEL];
__device__ float g_a    [MROWS * DMODEL];     // ctx * sigmoid(gated)
__device__ float g_x2   [MROWS * DMODEL];
__device__ float g_y    [MROWS * DMODEL];
__device__ float g_ffh  [MROWS * 2 * DMODEL];

// ---------------- helpers ----------------
__device__ __forceinline__ float warp_sum(float v) {
    #pragma unroll
    for (int o = 16; o > 0; o >>= 1) v += __shfl_xor_sync(0xffffffffu, v, o);
    return v;
}
__device__ __forceinline__ float warp_max(float v) {
    #pragma unroll
    for (int o = 16; o > 0; o >>= 1) v = fmaxf(v, __shfl_xor_sync(0xffffffffu, v, o));
    return v;
}

// ---------------- LayerNorm: one block per row of 768 ----------------
__global__ __launch_bounds__(256) void ln_kernel(
    const float* __restrict__ x, const float* __restrict__ gw,
    const float* __restrict__ bw, float* __restrict__ out)
{
    int row = blockIdx.x;
    int tid = threadIdx.x;
    const float* xr = x + (size_t)row * DMODEL;
    float v0 = xr[tid], v1 = xr[tid + 256], v2 = xr[tid + 512];
    float s  = v0 + v1 + v2;
    float s2 = v0 * v0 + v1 * v1 + v2 * v2;
    __shared__ float sm[8], sm2[8], stat[2];
    float ws = warp_sum(s), ws2 = warp_sum(s2);
    int wid = tid >> 5, lane = tid & 31;
    if (!lane) { sm[wid] = ws; sm2[wid] = ws2; }
    __syncthreads();
    if (tid == 0) {
        float S = 0.f, S2 = 0.f;
        #pragma unroll
        for (int i = 0; i < 8; ++i) { S += sm[i]; S2 += sm2[i]; }
        float mu  = S * (1.f / DMODEL);
        float var = S2 * (1.f / DMODEL) - mu * mu;
        stat[0] = mu;
        stat[1] = rsqrtf(var + 1e-5f);
    }
    __syncthreads();
    float mu = stat[0], rstd = stat[1];
    float* orow = out + (size_t)row * DMODEL;
    orow[tid]       = (v0 - mu) * rstd * gw[tid]       + bw[tid];
    orow[tid + 256] = (v1 - mu) * rstd * gw[tid + 256] + bw[tid + 256];
    orow[tid + 512] = (v2 - mu) * rstd * gw[tid + 512] + bw[tid + 512];
}

// ---------------- generic SGEMM: C = act(A[M,K]@W[K,N] + bias) (+ res) ----
// 64x64 tile, BK=16, 256 threads, 4x4 per-thread micro-tile.
template<int ACT, bool RES>
__global__ __launch_bounds__(256) void gemm_kernel(
    const float* __restrict__ A, const float* __restrict__ W,
    const float* __restrict__ bias, const float* __restrict__ res,
    float* __restrict__ C, int M, int N, int K)
{
    __shared__ float As[16][64];
    __shared__ float Bs[16][64];
    int t  = threadIdx.x;
    int bm = blockIdx.y << 6;
    int bn = blockIdx.x << 6;
    int ty = t >> 4, tx = t & 15;
    int arow = t >> 2,  acol = (t & 3) << 2;
    int brow = t >> 4,  bcol = (t & 15) << 2;
    const float* Ap = A + (size_t)(bm + arow) * K + acol;
    const float* Wp = W + (size_t)brow * N + bn + bcol;
    float acc[4][4] = {};
    for (int k0 = 0; k0 < K; k0 += 16) {
        float4 av = *reinterpret_cast<const float4*>(Ap + k0);
        As[acol + 0][arow] = av.x;
        As[acol + 1][arow] = av.y;
        As[acol + 2][arow] = av.z;
        As[acol + 3][arow] = av.w;
        *reinterpret_cast<float4*>(&Bs[brow][bcol]) =
            *reinterpret_cast<const float4*>(Wp + (size_t)k0 * N);
        __syncthreads();
        #pragma unroll
        for (int kk = 0; kk < 16; ++kk) {
            float4 a = *reinterpret_cast<const float4*>(&As[kk][ty << 2]);
            float4 b = *reinterpret_cast<const float4*>(&Bs[kk][tx << 2]);
            acc[0][0] = fmaf(a.x, b.x, acc[0][0]);
            acc[0][1] = fmaf(a.x, b.y, acc[0][1]);
            acc[0][2] = fmaf(a.x, b.z, acc[0][2]);
            acc[0][3] = fmaf(a.x, b.w, acc[0][3]);
            acc[1][0] = fmaf(a.y, b.x, acc[1][0]);
            acc[1][1] = fmaf(a.y, b.y, acc[1][1]);
            acc[1][2] = fmaf(a.y, b.z, acc[1][2]);
            acc[1][3] = fmaf(a.y, b.w, acc[1][3]);
            acc[2][0] = fmaf(a.z, b.x, acc[2][0]);
            acc[2][1] = fmaf(a.z, b.y, acc[2][1]);
            acc[2][2] = fmaf(a.z, b.z, acc[2][2]);
            acc[2][3] = fmaf(a.z, b.w, acc[2][3]);
            acc[3][0] = fmaf(a.w, b.x, acc[3][0]);
            acc[3][1] = fmaf(a.w, b.y, acc[3][1]);
            acc[3][2] = fmaf(a.w, b.z, acc[3][2]);
            acc[3][3] = fmaf(a.w, b.w, acc[3][3]);
        }
        __syncthreads();
    }
    #pragma unroll
    for (int i = 0; i < 4; ++i) {
        int row = bm + (ty << 2) + i;
        #pragma unroll
        for (int j = 0; j < 4; ++j) {
            int col = bn + (tx << 2) + j;
            float v = acc[i][j] + bias[col];
            if (ACT == 1) v = v / (1.f + __expf(-v));                      // silu
            if (ACT == 2) v = 0.5f * v * (1.f + erff(v * 0.70710678118654752f)); // gelu exact
            if (RES) v += res[(size_t)row * N + col];
            C[(size_t)row * N + col] = v;
        }
    }
}

// ---------------- fused distance-bias MLP (the 30-GFLOP monster) ---------
// bias[b,i,j,h] = silu(dist[b,i,j,:] @ W1 + b1) @ W2 + b2, stored [b][h][i][j]
// One block per (b,i): 256 threads, ONE j-row per thread (dist row in 64 regs,
// ~110 regs total -> 2 blocks/SM = 16 warps/SM). W1 chunk transposed in smem
// ([c][d], stride 68 = float4-aligned), written via STS.128 (conflict-free
// per 8-lane phase: banks 4c+d distinct for c=0..7), read via LDS.128
// broadcast. 4 independent h-accumulators to shorten FMA dep chains.
#define W1STRIDE 68
__global__ __launch_bounds__(256, 2) void rbias_kernel(
    const float* __restrict__ dist, const float* __restrict__ W1,
    const float* __restrict__ b1,   const float* __restrict__ W2,
    const float* __restrict__ b2,   float* __restrict__ biasT)
{
    int bi  = blockIdx.x;            // b*256 + i
    int bb  = bi >> 8, ii = bi & 255;
    int tid = threadIdx.x;

    __shared__ float sW1[64 * W1STRIDE]; // [c][d] transposed, padded stride
    __shared__ float sW2[64 * 12];       // [c][o]
    __shared__ float sb1[64];

    // this thread's dist row (j = tid)
    float dr[64];
    const float* dp = dist + (((size_t)bi << 8) + tid) * DDIM;
    #pragma unroll
    for (int q = 0; q < 16; ++q) {
        float4 t4 = *reinterpret_cast<const float4*>(dp + q * 4);
        dr[q * 4 + 0] = t4.x; dr[q * 4 + 1] = t4.y;
        dr[q * 4 + 2] = t4.z; dr[q * 4 + 3] = t4.w;
    }

    float acc[12] = {};
    int c_ld  = tid & 63;            // hidden unit this thread loads
    int d_grp = (tid >> 6) << 2;     // 0,4,8,12

    #pragma unroll 1
    for (int cc = 0; cc < 12; ++cc) {
        // W1 chunk -> smem transposed. Each global LDG is coalesced across
        // lanes (consecutive c, fixed d); each smem write is one STS.128.
        const float* w1g = W1 + (cc << 6) + c_ld;
        #pragma unroll
        for (int rep = 0; rep < 4; ++rep) {
            int d = rep * 16 + d_grp;
            float4 v;
            v.x = w1g[(size_t)(d + 0) * DMODEL];
            v.y = w1g[(size_t)(d + 1) * DMODEL];
            v.z = w1g[(size_t)(d + 2) * DMODEL];
            v.w = w1g[(size_t)(d + 3) * DMODEL];
            *reinterpret_cast<float4*>(&sW1[c_ld * W1STRIDE + d]) = v;
        }
        for (int idx = tid; idx < 768; idx += 256)
            sW2[idx] = W2[(size_t)cc * 768 + idx];   // rows cc*64..+63 contiguous
        if (tid < 64) sb1[tid] = b1[(cc << 6) + tid];
        __syncthreads();

        #pragma unroll 1
        for (int c = 0; c < 64; ++c) {
            float ha = sb1[c], hb = 0.f, hc = 0.f, hd = 0.f;
            const float4* w1c = reinterpret_cast<const float4*>(sW1 + c * W1STRIDE);
            #pragma unroll
            for (int q = 0; q < 16; q += 2) {
                float4 wA = w1c[q];
                float4 wB = w1c[q + 1];
                int d = q << 2;
                ha = fmaf(dr[d + 0], wA.x, ha);
                hb = fmaf(dr[d + 1], wA.y, hb);
                hc = fmaf(dr[d + 2], wA.z, hc);
                hd = fmaf(dr[d + 3], wA.w, hd);
                ha = fmaf(dr[d + 4], wB.x, ha);
                hb = fmaf(dr[d + 5], wB.y, hb);
                hc = fmaf(dr[d + 6], wB.z, hc);
                hd = fmaf(dr[d + 7], wB.w, hd);
            }
            float h = (ha + hb) + (hc + hd);
            float s = h / (1.f + __expf(-h));
            const float4* w2c = reinterpret_cast<const float4*>(sW2 + c * 12);
            float4 w0 = w2c[0], w1v = w2c[1], w2v = w2c[2];
            acc[0]  = fmaf(s, w0.x,  acc[0]);
            acc[1]  = fmaf(s, w0.y,  acc[1]);
            acc[2]  = fmaf(s, w0.z,  acc[2]);
            acc[3]  = fmaf(s, w0.w,  acc[3]);
            acc[4]  = fmaf(s, w1v.x, acc[4]);
            acc[5]  = fmaf(s, w1v.y, acc[5]);
            acc[6]  = fmaf(s, w1v.z, acc[6]);
            acc[7]  = fmaf(s, w1v.w, acc[7]);
            acc[8]  = fmaf(s, w2v.x, acc[8]);
            acc[9]  = fmaf(s, w2v.y, acc[9]);
            acc[10] = fmaf(s, w2v.z, acc[10]);
            acc[11] = fmaf(s, w2v.w, acc[11]);
        }
        __syncthreads();
    }

    #pragma unroll
    for (int o = 0; o < 12; ++o) {
        size_t base = (((size_t)bb * NHEAD + o) * NSEQ + ii) * NSEQ;
        biasT[base + tid] = acc[o] + b2[o];
    }
}

// ---------------- attention: one block per (b,h,i) query row -------------
__global__ __launch_bounds__(128) void attn_kernel(
    const float* __restrict__ qkv, const float* __restrict__ biasT,
    const int* __restrict__ mask, float* __restrict__ ctx)
{
    int i = blockIdx.x, h = blockIdx.y, b = blockIdx.z;
    int tid = threadIdx.x;
    __shared__ float qs[64];
    __shared__ float ps[256];
    __shared__ float red[4];
    __shared__ float part[2][64];

    size_t qoff = ((size_t)(b * NSEQ + i)) * 2304 + (size_t)h * HDIM;
    if (tid < 64) qs[tid] = qkv[qoff + tid];
    __syncthreads();

    float lv[2];
    #pragma unroll
    for (int u = 0; u < 2; ++u) {
        int j = tid + (u << 7);
        const float* kp = qkv + ((size_t)(b * NSEQ + j)) * 2304 + DMODEL + h * HDIM;
        float a0 = 0.f, a1 = 0.f;
        #pragma unroll
        for (int d = 0; d < 64; d += 4) {
            float4 kv4 = *reinterpret_cast<const float4*>(kp + d);
            a0 = fmaf(qs[d],     kv4.x, a0);
            a1 = fmaf(qs[d + 1], kv4.y, a1);
            a0 = fmaf(qs[d + 2], kv4.z, a0);
            a1 = fmaf(qs[d + 3], kv4.w, a1);
        }
        float lg = (a0 + a1) * 0.125f
                 + biasT[(((size_t)b * NHEAD + h) * NSEQ + i) * NSEQ + j];
        if (mask[((size_t)(b * NSEQ + i)) * NSEQ + j] == 0) lg = -1e30f;
        lv[u] = lg;
    }

    int wid = tid >> 5, lane = tid & 31;
    float m = warp_max(fmaxf(lv[0], lv[1]));
    if (!lane) red[wid] = m;
    __syncthreads();
    m = fmaxf(fmaxf(red[0], red[1]), fmaxf(red[2], red[3]));
    __syncthreads();                     // red reuse below

    float e0 = __expf(lv[0] - m), e1 = __expf(lv[1] - m);
    ps[tid] = e0; ps[tid + 128] = e1;
    float s = warp_sum(e0 + e1);
    if (!lane) red[wid] = s;
    __syncthreads();
    float inv = 1.f / (red[0] + red[1] + red[2] + red[3]);

    int d = tid & 63, pr = tid >> 6;
    const float* vp = qkv + 2 * DMODEL + (size_t)h * HDIM + d;
    float a0 = 0.f, a1 = 0.f;
    int j0 = pr << 7;
    #pragma unroll 4
    for (int j = j0; j < j0 + 128; j += 2) {
        a0 = fmaf(ps[j],     vp[((size_t)(b * NSEQ + j)) * 2304],     a0);
        a1 = fmaf(ps[j + 1], vp[((size_t)(b * NSEQ + j + 1)) * 2304], a1);
    }
    part[pr][d] = a0 + a1;
    __syncthreads();
    if (tid < 64)
        ctx[((size_t)(b * NSEQ + i)) * DMODEL + h * HDIM + tid] =
            (part[0][tid] + part[1][tid]) * inv;
}

// ---------------- a = ctx * sigmoid(gated) ----------------
__global__ __launch_bounds__(256) void gate_mul_kernel(
    const float* __restrict__ ctx, const float* __restrict__ gated,
    float* __restrict__ a, int n)
{
    int idx = blockIdx.x * 256 + threadIdx.x;
    if (idx < n) {
        float g = gated[idx];
        a[idx] = ctx[idx] * (1.f / (1.f + __expf(-g)));
    }
}

// ---------------- launch ----------------
extern "C" void kernel_launch(void* const* d_in, const int* in_sizes, int n_in,
                              void* d_out, int out_size)
{
    const float* x       = (const float*)d_in[0];
    const float* dist    = (const float*)d_in[1];
    const int*   mask    = (const int*)  d_in[2];
    const float* qkv_w   = (const float*)d_in[3];
    const float* qkv_b   = (const float*)d_in[4];
    const float* out_w   = (const float*)d_in[5];
    const float* out_b   = (const float*)d_in[6];
    const float* rb_w1   = (const float*)d_in[7];
    const float* rb_b1   = (const float*)d_in[8];
    const float* rb_w2   = (const float*)d_in[9];
    const float* rb_b2   = (const float*)d_in[10];
    const float* gate_w1 = (const float*)d_in[11];
    const float* gate_b1 = (const float*)d_in[12];
    const float* gate_w2 = (const float*)d_in[13];
    const float* gate_b2 = (const float*)d_in[14];
    const float* ff_w1   = (const float*)d_in[15];
    const float* ff_b1   = (const float*)d_in[16];
    const float* ff_w2   = (const float*)d_in[17];
    const float* ff_b2   = (const float*)d_in[18];
    const float* ln1_g   = (const float*)d_in[19];
    const float* ln1_b   = (const float*)d_in[20];
    const float* ln2_g   = (const float*)d_in[21];
    const float* ln2_b   = (const float*)d_in[22];
    float* out = (float*)d_out;

    float *xn, *qkv, *s1, *gated, *biasT, *ctx, *a, *x2, *y, *ffh;
    cudaGetSymbolAddress((void**)&xn,    g_xn);
    cudaGetSymbolAddress((void**)&qkv,   g_qkv);
    cudaGetSymbolAddress((void**)&s1,    g_s1);
    cudaGetSymbolAddress((void**)&gated, g_gated);
    cudaGetSymbolAddress((void**)&biasT, g_biasT);
    cudaGetSymbolAddress((void**)&ctx,   g_ctx);
    cudaGetSymbolAddress((void**)&a,     g_a);
    cudaGetSymbolAddress((void**)&x2,    g_x2);
    cudaGetSymbolAddress((void**)&y,     g_y);
    cudaGetSymbolAddress((void**)&ffh,   g_ffh);

    // LN1
    ln_kernel<<<MROWS, 256>>>(x, ln1_g, ln1_b, xn);
    // qkv = xn @ qkv_w + b
    gemm_kernel<0, false><<<dim3(36, 16), 256>>>(xn, qkv_w, qkv_b, nullptr, qkv,
                                                 MROWS, 3 * DMODEL, DMODEL);
    // s1 = silu(xn @ gate_w1 + b)
    gemm_kernel<1, false><<<dim3(12, 16), 256>>>(xn, gate_w1, gate_b1, nullptr, s1,
                                                 MROWS, DMODEL, DMODEL);
    // fused distance-bias MLP
    rbias_kernel<<<MROWS, 256>>>(dist, rb_w1, rb_b1, rb_w2, rb_b2, biasT);
    // attention
    attn_kernel<<<dim3(NSEQ, NHEAD, 4), 128>>>(qkv, biasT, mask, ctx);
    // gated = s1 @ gate_w2 + b
    gemm_kernel<0, false><<<dim3(12, 16), 256>>>(s1, gate_w2, gate_b2, nullptr, gated,
                                                 MROWS, DMODEL, DMODEL);
    // a = ctx * sigmoid(gated)
    gate_mul_kernel<<<(MROWS * DMODEL + 255) / 256, 256>>>(ctx, gated, a, MROWS * DMODEL);
    // x2 = x + a @ out_w + out_b
    gemm_kernel<0, true><<<dim3(12, 16), 256>>>(a, out_w, out_b, x, x2,
                                                MROWS, DMODEL, DMODEL);
    // LN2
    ln_kernel<<<MROWS, 256>>>(x2, ln2_g, ln2_b, y);
    // ffh = gelu(y @ ff_w1 + b)
    gemm_kernel<2, false><<<dim3(24, 16), 256>>>(y, ff_w1, ff_b1, nullptr, ffh,
                                                 MROWS, 2 * DMODEL, DMODEL);
    // out = x2 + ffh @ ff_w2 + b
    gemm_kernel<0, true><<<dim3(12, 16), 256>>>(ffh, ff_w2, ff_b2, x2, out,
                                                MROWS, DMODEL, 2 * DMODEL);
}